// round 17
// baseline (speedup 1.0000x reference)
#include <cuda_runtime.h>
#include <cuda_fp16.h>
#include <math.h>
#include <stdint.h>

#define D_MODEL 1024
#define BATCH   4
#define SEQ     1024
#define NHEADS  16
#define HDIM    64
#define HMLP    4096
#define ROWS    (BATCH*SEQ)     // 4096
#define HROWS   (ROWS/2)        // 2048 (two batches per pipeline)

// ---------------- scratch (device globals; no allocs allowed) ----------------
__device__ __half h_ln   [ROWS * D_MODEL];
__device__ __half h_qkv  [ROWS * 3 * D_MODEL];
__device__ __half h_kv   [ROWS * 2 * D_MODEL];
__device__ __half h_attn [ROWS * D_MODEL];
__device__ __half h_q    [ROWS * D_MODEL];
__device__ float  g_cross[ROWS * D_MODEL];
__device__ __half h_mlp  [ROWS * HMLP];
__device__ float  g_xs   [(size_t)BATCH * SEQ * SEQ];
__device__ __half h_p    [(size_t)BATCH * SEQ * SEQ];
__device__ __half h_z    [ROWS * D_MODEL];
__device__ __half h_wt_qkv[3 * D_MODEL * D_MODEL];
__device__ __half h_wt_o  [D_MODEL * D_MODEL];
__device__ __half h_wt_kv [2 * D_MODEL * D_MODEL];
__device__ __half h_wt_m1 [HMLP * D_MODEL];
__device__ __half h_wt_m2 [D_MODEL * HMLP];
__device__ __half h_vt_self [BATCH * NHEADS * HDIM * SEQ];
__device__ __half h_vt_cross[(size_t)BATCH * D_MODEL * SEQ];

__device__ __forceinline__ float gelu_tanh(float c) {
    float t = 0.7978845608028654f * (c + 0.044715f * c * c * c);
    return 0.5f * c * (1.0f + tanhf(t));
}
__device__ __forceinline__ void mma_f16(float* d, const uint32_t* a, const uint32_t* b) {
    asm volatile("mma.sync.aligned.m16n8k16.row.col.f32.f16.f16.f32 "
        "{%0,%1,%2,%3}, {%4,%5,%6,%7}, {%8,%9}, {%0,%1,%2,%3};"
        : "+f"(d[0]), "+f"(d[1]), "+f"(d[2]), "+f"(d[3])
        : "r"(a[0]), "r"(a[1]), "r"(a[2]), "r"(a[3]), "r"(b[0]), "r"(b[1]));
}
__device__ __forceinline__ void ldsm_x4(uint32_t& r0, uint32_t& r1, uint32_t& r2, uint32_t& r3,
                                        uint32_t addr) {
    asm volatile("ldmatrix.sync.aligned.m8n8.x4.shared.b16 {%0,%1,%2,%3}, [%4];"
        : "=r"(r0), "=r"(r1), "=r"(r2), "=r"(r3) : "r"(addr));
}
__device__ __forceinline__ void cp16(uint32_t smem, const void* g) {
    asm volatile("cp.async.cg.shared.global [%0], [%1], 16;" :: "r"(smem), "l"(g));
}
__device__ __forceinline__ uint32_t smem_u32(const void* p) {
    return (uint32_t)__cvta_generic_to_shared(p);
}
__device__ __forceinline__ void store2(__half* p, float a, float b) {
    *(__half2*)p = __floats2half2_rn(a, b);
}
__device__ __forceinline__ void store2(float* p, float a, float b) {
    float2 v; v.x = a; v.y = b; *(float2*)p = v;
}
__device__ __forceinline__ uint32_t packh2(float a, float b) {
    __half2 h = __floats2half2_rn(a, b);
    return *(uint32_t*)&h;
}

// ------------- single-pass layernorm (fp32 in -> fp16 out) + optional z cvt ----
__global__ void ln_kernel(const float* __restrict__ x, const float* __restrict__ g,
                          const float* __restrict__ b, __half* __restrict__ out,
                          const float* __restrict__ zsrc, __half* __restrict__ zdst) {
    int row = blockIdx.x;
    int tid = threadIdx.x;
    const float* xr = x + (size_t)row * D_MODEL;
    float4 v = *(const float4*)(xr + tid * 4);
    if (zsrc) {
        const float* zr = zsrc + (size_t)row * D_MODEL;
        __half* zo = zdst + (size_t)row * D_MODEL;
        float4 a = *(const float4*)(zr + tid * 4);
        __half2 h[2];
        h[0] = __floats2half2_rn(a.x, a.y); h[1] = __floats2half2_rn(a.z, a.w);
        *(uint2*)(zo + tid * 4) = *(uint2*)h;
    }
    float s  = v.x + v.y + v.z + v.w;
    float s2 = v.x * v.x + v.y * v.y + v.z * v.z + v.w * v.w;
    __shared__ float rs[8], rs2[8];
    for (int o = 16; o > 0; o >>= 1) {
        s  += __shfl_xor_sync(0xffffffff, s,  o);
        s2 += __shfl_xor_sync(0xffffffff, s2, o);
    }
    if ((tid & 31) == 0) { rs[tid >> 5] = s; rs2[tid >> 5] = s2; }
    __syncthreads();
    if (tid < 32) {
        float a  = (tid < 8) ? rs[tid]  : 0.f;
        float a2 = (tid < 8) ? rs2[tid] : 0.f;
        for (int o = 4; o > 0; o >>= 1) {
            a  += __shfl_xor_sync(0xffffffff, a,  o);
            a2 += __shfl_xor_sync(0xffffffff, a2, o);
        }
        rs[0] = a; rs2[0] = a2;
    }
    __syncthreads();
    float mu  = rs[0]  * (1.0f / D_MODEL);
    float var = rs2[0] * (1.0f / D_MODEL) - mu * mu;
    float inv = rsqrtf(var + 1e-5f);
    float4 gg = *(const float4*)(g + tid * 4);
    float4 bb = *(const float4*)(b + tid * 4);
    __half2 h[2];
    h[0] = __floats2half2_rn((v.x - mu) * inv * gg.x + bb.x,
                             (v.y - mu) * inv * gg.y + bb.y);
    h[1] = __floats2half2_rn((v.z - mu) * inv * gg.z + bb.z,
                             (v.w - mu) * inv * gg.w + bb.w);
    *(uint2*)(out + (size_t)row * D_MODEL + tid * 4) = *(uint2*)h;
}

// ---------------- softmax fp32 in -> fp16 out (cross) ----------------
__global__ void softmax_f2h(const float* __restrict__ S, __half* __restrict__ P) {
    const float* row = S + (size_t)blockIdx.x * 1024;
    __half* prow = P + (size_t)blockIdx.x * 1024;
    int tid = threadIdx.x;
    float4 v = *(const float4*)(row + tid * 4);
    float mx = fmaxf(fmaxf(v.x, v.y), fmaxf(v.z, v.w));
    __shared__ float red[32];
    for (int o = 16; o > 0; o >>= 1) mx = fmaxf(mx, __shfl_xor_sync(0xffffffff, mx, o));
    if ((tid & 31) == 0) red[tid >> 5] = mx;
    __syncthreads();
    if (tid < 32) {
        float m = (tid < 8) ? red[tid] : -1e30f;
        for (int o = 4; o > 0; o >>= 1) m = fmaxf(m, __shfl_xor_sync(0xffffffff, m, o));
        red[0] = m;
    }
    __syncthreads();
    mx = red[0];
    v.x = expf(v.x - mx); v.y = expf(v.y - mx); v.z = expf(v.z - mx); v.w = expf(v.w - mx);
    float s = v.x + v.y + v.z + v.w;
    for (int o = 16; o > 0; o >>= 1) s += __shfl_xor_sync(0xffffffff, s, o);
    __syncthreads();
    if ((tid & 31) == 0) red[tid >> 5] = s;
    __syncthreads();
    if (tid < 32) {
        float t = (tid < 8) ? red[tid] : 0.f;
        for (int o = 4; o > 0; o >>= 1) t += __shfl_xor_sync(0xffffffff, t, o);
        red[0] = t;
    }
    __syncthreads();
    float inv = 1.0f / red[0];
    __half2 h2[2];
    h2[0] = __floats2half2_rn(v.x * inv, v.y * inv);
    h2[1] = __floats2half2_rn(v.z * inv, v.w * inv);
    *(uint2*)(prow + tid * 4) = *(uint2*)h2;
}

// ---------------- fast 64x64 batched transpose (TS in -> half out) ------------
template <typename TS>
__device__ __forceinline__ void ld4h(const TS* p, __half* v);
template <>
__device__ __forceinline__ void ld4h<float>(const float* p, __half* v) {
    float4 f = *(const float4*)p;
    v[0] = __float2half(f.x); v[1] = __float2half(f.y);
    v[2] = __float2half(f.z); v[3] = __float2half(f.w);
}
template <>
__device__ __forceinline__ void ld4h<__half>(const __half* p, __half* v) {
    uint2 u = *(const uint2*)p;
    *(uint32_t*)&v[0] = u.x; *(uint32_t*)&v[2] = u.y;
}

template <typename TS>
__global__ void __launch_bounds__(256)
transpose64(const TS* __restrict__ srcb, __half* __restrict__ dstb,
            int lds, int ldd, long sSb, long sSh, long sDb, long sDh, int nh) {
    __shared__ __half tile[64][66];
    int z = blockIdx.z, b = z / nh, h = z - b * nh;
    const TS* src = srcb + (size_t)b * sSb + (size_t)h * sSh;
    __half* dst = dstb + (size_t)b * sDb + (size_t)h * sDh;
    int x0 = blockIdx.x * 64;
    int y0 = blockIdx.y * 64;
    int tx = threadIdx.x & 15, ty = threadIdx.x >> 4;
    #pragma unroll
    for (int i = 0; i < 4; i++) {
        int row = y0 + ty + i * 16;
        __half v[4];
        ld4h<TS>(src + (size_t)row * lds + x0 + tx * 4, v);
        tile[tx * 4 + 0][ty + i * 16] = v[0];
        tile[tx * 4 + 1][ty + i * 16] = v[1];
        tile[tx * 4 + 2][ty + i * 16] = v[2];
        tile[tx * 4 + 3][ty + i * 16] = v[3];
    }
    __syncthreads();
    #pragma unroll
    for (int i = 0; i < 4; i++) {
        int drow = x0 + ty + i * 16;
        __half2 p0, p1;
        p0.x = tile[ty + i * 16][tx * 4 + 0]; p0.y = tile[ty + i * 16][tx * 4 + 1];
        p1.x = tile[ty + i * 16][tx * 4 + 2]; p1.y = tile[ty + i * 16][tx * 4 + 3];
        uint2 o; o.x = *(uint32_t*)&p0; o.y = *(uint32_t*)&p1;
        *(uint2*)(dst + (size_t)drow * ldd + y0 + tx * 4) = o;
    }
}

// ========== flash self-attention v2: cp.async 3-stage ring + ldmatrix ==========
#define FLASH_SMEM (16384 + 3 * 16384)   // 65536 B

__global__ void __launch_bounds__(256)
flash_self(const __half* __restrict__ qkvg, const __half* __restrict__ vtsg,
           __half* __restrict__ attng) {
    extern __shared__ __align__(16) char fsmc[];
    uint32_t sq = smem_u32(fsmc);

    int tid = threadIdx.x, lane = tid & 31, warp = tid >> 5;
    int bh = blockIdx.y, b = bh >> 4, h = bh & 15;
    const __half* Qg = qkvg + (size_t)b * SEQ * 3 * D_MODEL
                     + (size_t)blockIdx.x * 128 * 3 * D_MODEL + h * HDIM;
    const __half* Kg = qkvg + (size_t)b * SEQ * 3 * D_MODEL + D_MODEL + h * HDIM;
    const __half* Vt = vtsg + (size_t)bh * HDIM * SEQ;
    __half* Og = attng + (size_t)b * SEQ * D_MODEL
               + (size_t)blockIdx.x * 128 * D_MODEL + h * HDIM;

    auto issue_kv = [&](int kb) {
        uint32_t base = sq + 16384 + (kb % 3) * 16384;
        #pragma unroll
        for (int i = 0; i < 2; i++) {
            int f = i * 256 + tid, row = f >> 3, ch = f & 7;
            uint32_t sw = (ch ^ (row & 7)) * 16;
            cp16(base + row * 128 + sw,
                 Kg + (size_t)(kb * 64 + row) * 3 * D_MODEL + ch * 8);
            cp16(base + 8192 + row * 128 + sw,
                 Vt + (size_t)row * SEQ + kb * 64 + ch * 8);
        }
        asm volatile("cp.async.commit_group;");
    };

    #pragma unroll
    for (int i = 0; i < 4; i++) {
        int f = i * 256 + tid, row = f >> 3, ch = f & 7;
        cp16(sq + row * 128 + ((ch ^ (row & 7)) * 16),
             Qg + (size_t)row * 3 * D_MODEL + ch * 8);
    }
    issue_kv(0);
    issue_kv(1);

    uint32_t qa[4][4];
    float oacc[8][4];
    #pragma unroll
    for (int ni = 0; ni < 8; ni++)
        #pragma unroll
        for (int c = 0; c < 4; c++) oacc[ni][c] = 0.f;
    float m0 = -1e30f, m1 = -1e30f, l0 = 0.f, l1 = 0.f;

    int frag_r = lane & 15;
    int csel = lane >> 4;
    int sw7 = frag_r & 7;

    for (int kb = 0; kb < 16; kb++) {
        if (kb < 15) asm volatile("cp.async.wait_group 1;");
        else         asm volatile("cp.async.wait_group 0;");
        __syncthreads();
        if (kb == 0) {
            int qr = warp * 16 + frag_r;
            #pragma unroll
            for (int kk = 0; kk < 4; kk++) {
                int ch = kk * 2 + csel;
                ldsm_x4(qa[kk][0], qa[kk][1], qa[kk][2], qa[kk][3],
                        sq + qr * 128 + ((ch ^ sw7) * 16));
            }
        }
        if (kb + 2 < 16) issue_kv(kb + 2);

        uint32_t kbase = sq + 16384 + (kb % 3) * 16384;
        uint32_t vbase = kbase + 8192;

        float sacc[8][4];
        #pragma unroll
        for (int ni = 0; ni < 8; ni++)
            #pragma unroll
            for (int c = 0; c < 4; c++) sacc[ni][c] = 0.f;
        #pragma unroll
        for (int kk = 0; kk < 4; kk++) {
            int ch = kk * 2 + csel;
            uint32_t breg[4][4];
            #pragma unroll
            for (int p = 0; p < 4; p++) {
                int r = p * 16 + frag_r;
                ldsm_x4(breg[p][0], breg[p][1], breg[p][2], breg[p][3],
                        kbase + r * 128 + ((ch ^ sw7) * 16));
            }
            #pragma unroll
            for (int ni = 0; ni < 8; ni++) {
                uint32_t bfr[2] = { breg[ni >> 1][ni & 1], breg[ni >> 1][(ni & 1) + 2] };
                mma_f16(sacc[ni], qa[kk], bfr);
            }
        }

        float mx0 = -1e30f, mx1 = -1e30f;
        #pragma unroll
        for (int ni = 0; ni < 8; ni++) {
            mx0 = fmaxf(mx0, fmaxf(sacc[ni][0], sacc[ni][1]));
            mx1 = fmaxf(mx1, fmaxf(sacc[ni][2], sacc[ni][3]));
        }
        mx0 = fmaxf(mx0, __shfl_xor_sync(0xffffffff, mx0, 1));
        mx0 = fmaxf(mx0, __shfl_xor_sync(0xffffffff, mx0, 2));
        mx1 = fmaxf(mx1, __shfl_xor_sync(0xffffffff, mx1, 1));
        mx1 = fmaxf(mx1, __shfl_xor_sync(0xffffffff, mx1, 2));
        float nm0 = fmaxf(m0, mx0 * 0.125f);
        float nm1 = fmaxf(m1, mx1 * 0.125f);
        float a0 = __expf(m0 - nm0);
        float a1 = __expf(m1 - nm1);
        m0 = nm0; m1 = nm1;

        uint32_t pw0[8], pw1[8];
        float s0 = 0.f, s1 = 0.f;
        #pragma unroll
        for (int ni = 0; ni < 8; ni++) {
            float p0 = __expf(sacc[ni][0] * 0.125f - nm0);
            float p1 = __expf(sacc[ni][1] * 0.125f - nm0);
            float p2 = __expf(sacc[ni][2] * 0.125f - nm1);
            float p3 = __expf(sacc[ni][3] * 0.125f - nm1);
            s0 += p0 + p1; s1 += p2 + p3;
            pw0[ni] = packh2(p0, p1);
            pw1[ni] = packh2(p2, p3);
        }
        s0 += __shfl_xor_sync(0xffffffff, s0, 1);
        s0 += __shfl_xor_sync(0xffffffff, s0, 2);
        s1 += __shfl_xor_sync(0xffffffff, s1, 1);
        s1 += __shfl_xor_sync(0xffffffff, s1, 2);
        l0 = l0 * a0 + s0;
        l1 = l1 * a1 + s1;
        #pragma unroll
        for (int ni = 0; ni < 8; ni++) {
            oacc[ni][0] *= a0; oacc[ni][1] *= a0;
            oacc[ni][2] *= a1; oacc[ni][3] *= a1;
        }

        #pragma unroll
        for (int kp = 0; kp < 4; kp++) {
            int ch = kp * 2 + csel;
            uint32_t pa[4] = { pw0[2 * kp], pw1[2 * kp], pw0[2 * kp + 1], pw1[2 * kp + 1] };
            uint32_t breg[4][4];
            #pragma unroll
            for (int p = 0; p < 4; p++) {
                int r = p * 16 + frag_r;
                ldsm_x4(breg[p][0], breg[p][1], breg[p][2], breg[p][3],
                        vbase + r * 128 + ((ch ^ sw7) * 16));
            }
            #pragma unroll
            for (int ni = 0; ni < 8; ni++) {
                uint32_t bfr[2] = { breg[ni >> 1][ni & 1], breg[ni >> 1][(ni & 1) + 2] };
                mma_f16(oacc[ni], pa, bfr);
            }
        }
    }

    float i0 = 1.0f / l0, i1 = 1.0f / l1;
    int r = warp * 16 + (lane >> 2);
    #pragma unroll
    for (int ni = 0; ni < 8; ni++) {
        int col = ni * 8 + 2 * (lane & 3);
        store2(Og + (size_t)r * D_MODEL + col,       oacc[ni][0] * i0, oacc[ni][1] * i0);
        store2(Og + (size_t)(r + 8) * D_MODEL + col, oacc[ni][2] * i1, oacc[ni][3] * i1);
    }
}

// ======= fp16 GEMM: cp.async + swizzle + ldmatrix, 128 x TN tile (TN=256|128) ==
#define NSTAGE 4
#define A_BYTES 16384

template <typename CT, int TN>
__global__ void __launch_bounds__(256)
mm2(const __half* __restrict__ Abase, const __half* __restrict__ Bbase,
    const float* __restrict__ bias, const float* __restrict__ resbase,
    CT* __restrict__ Cbase, int K, int lda, int ldb, int ldc,
    long sAb, long sBb, long sCb, float scale, int act) {
    constexpr int B_BYTES = TN * 128;
    constexpr int STAGEB  = A_BYTES + B_BYTES;
    constexpr int WNT = TN / 4;
    constexpr int PB  = WNT / 16;
    constexpr int NI  = WNT / 8;
    constexpr int NBLD = TN / 32;

    extern __shared__ __align__(16) char smc[];
    uint32_t sb = smem_u32(smc);

    int tid = threadIdx.x, lane = tid & 31, warp = tid >> 5;
    int wy = warp & 1, wx = warp >> 1;
    int z = blockIdx.z;
    const __half* A = Abase + (size_t)z * sAb + (size_t)blockIdx.y * 128 * lda;
    const __half* B = Bbase + (size_t)z * sBb + (size_t)blockIdx.x * TN * ldb;
    CT* C = Cbase + (size_t)z * sCb;
    const float* res = resbase ? resbase + (size_t)z * sCb : nullptr;
    int m0 = blockIdx.y * 128, n0 = blockIdx.x * TN;

    float acc[4][NI][4];
    #pragma unroll
    for (int mi = 0; mi < 4; mi++)
        #pragma unroll
        for (int ni = 0; ni < NI; ni++)
            #pragma unroll
            for (int c = 0; c < 4; c++) acc[mi][ni][c] = 0.f;

    int lrow = tid >> 3;
    int lc   = tid & 7;
    auto issue_stage = [&](int kb, int stage) {
        uint32_t as = sb + stage * STAGEB;
        uint32_t bs = as + A_BYTES;
        int koff = kb * 64 + lc * 8;
        #pragma unroll
        for (int i = 0; i < 4; i++) {
            int row = lrow + i * 32;
            cp16(as + row * 128 + ((lc ^ (row & 7)) * 16),
                 A + (size_t)row * lda + koff);
        }
        #pragma unroll
        for (int i = 0; i < NBLD; i++) {
            int row = lrow + i * 32;
            cp16(bs + row * 128 + ((lc ^ (row & 7)) * 16),
                 B + (size_t)row * ldb + koff);
        }
        asm volatile("cp.async.commit_group;");
    };

    int nkb = K >> 6;
    issue_stage(0, 0);
    issue_stage(1, 1);
    if (nkb > 2) issue_stage(2, 2);
    else asm volatile("cp.async.commit_group;");

    int arow = wy * 64 + (lane & 15);
    int brow = wx * WNT + (lane & 15);
    int csel = lane >> 4;

    for (int kb = 0; kb < nkb; kb++) {
        asm volatile("cp.async.wait_group 2;");
        __syncthreads();
        int stage = kb % NSTAGE;
        if (kb + 3 < nkb) issue_stage(kb + 3, (kb + 3) % NSTAGE);
        else asm volatile("cp.async.commit_group;");

        uint32_t as = sb + stage * STAGEB;
        uint32_t bs = as + A_BYTES;
        #pragma unroll
        for (int kk = 0; kk < 4; kk++) {
            int ch = kk * 2 + csel;
            uint32_t afr[4][4], breg[PB][4];
            #pragma unroll
            for (int mi = 0; mi < 4; mi++) {
                int r = arow + mi * 16;
                ldsm_x4(afr[mi][0], afr[mi][1], afr[mi][2], afr[mi][3],
                        as + r * 128 + ((ch ^ (r & 7)) * 16));
            }
            #pragma unroll
            for (int p = 0; p < PB; p++) {
                int r = brow + p * 16;
                ldsm_x4(breg[p][0], breg[p][1], breg[p][2], breg[p][3],
                        bs + r * 128 + ((ch ^ (r & 7)) * 16));
            }
            #pragma unroll
            for (int mi = 0; mi < 4; mi++)
                #pragma unroll
                for (int ni = 0; ni < NI; ni++) {
                    uint32_t bfr[2] = { breg[ni >> 1][ni & 1], breg[ni >> 1][(ni & 1) + 2] };
                    mma_f16(acc[mi][ni], afr[mi], bfr);
                }
        }
    }

    #pragma unroll
    for (int mi = 0; mi < 4; mi++) {
        #pragma unroll
        for (int ni = 0; ni < NI; ni++) {
            int col = n0 + wx * WNT + ni * 8 + 2 * (lane & 3);
            #pragma unroll
            for (int half = 0; half < 2; half++) {
                int row = m0 + wy * 64 + mi * 16 + (lane >> 2) + half * 8;
                float c0 = acc[mi][ni][2 * half]     * scale;
                float c1 = acc[mi][ni][2 * half + 1] * scale;
                if (bias) { c0 += bias[col]; c1 += bias[col + 1]; }
                if (act == 1) { c0 = gelu_tanh(c0); c1 = gelu_tanh(c1); }
                if (res) {
                    float2 rv = *(const float2*)(res + (size_t)row * ldc + col);
                    c0 += rv.x; c1 += rv.y;
                }
                store2(C + (size_t)row * ldc + col, c0, c1);
            }
        }
    }
}

#define SMEM_T(TN) (NSTAGE * (A_BYTES + (TN) * 128))

// ======= mm3: 64x64 tile, 128 threads, 2x2 warps (warp tile 32x32) ===========
#define A3_BYTES 8192
#define STAGE3   (A3_BYTES + 8192)
#define SMEM3    (NSTAGE * STAGE3)   // 65536

template <typename CT>
__global__ void __launch_bounds__(128)
mm3(const __half* __restrict__ Abase, const __half* __restrict__ Bbase,
    const float* __restrict__ bias, const float* __restrict__ resbase,
    CT* __restrict__ Cbase, int K, int lda, int ldb, int ldc,
    long sAb, long sBb, long sCb, float scale, int act) {
    extern __shared__ __align__(16) char smc[];
    uint32_t sb = smem_u32(smc);

    int tid = threadIdx.x, lane = tid & 31, warp = tid >> 5;
    int wy = warp & 1, wx = warp >> 1;
    int z = blockIdx.z;
    const __half* A = Abase + (size_t)z * sAb + (size_t)blockIdx.y * 64 * lda;
    const __half* B = Bbase + (size_t)z * sBb + (size_t)blockIdx.x * 64 * ldb;
    CT* C = Cbase + (size_t)z * sCb;
    const float* res = resbase ? resbase + (size_t)z * sCb : nullptr;
    int m0 = blockIdx.y * 64, n0 = blockIdx.x * 64;

    float acc[2][4][4];
    #pragma unroll
    for (int mi = 0; mi < 2; mi++)
        #pragma unroll
        for (int ni = 0; ni < 4; ni++)
            #pragma unroll
            for (int c = 0; c < 4; c++) acc[mi][ni][c] = 0.f;

    int lrow = tid >> 3;
    int lc   = tid & 7;
    auto issue_stage = [&](int kb, int stage) {
        uint32_t as = sb + stage * STAGE3;
        uint32_t bs = as + A3_BYTES;
        int koff = kb * 64 + lc * 8;
        #pragma unroll
        for (int i = 0; i < 4; i++) {
            int row = lrow + i * 16;
            cp16(as + row * 128 + ((lc ^ (row & 7)) * 16),
                 A + (size_t)row * lda + koff);
        }
        #pragma unroll
        for (int i = 0; i < 4; i++) {
            int row = lrow + i * 16;
            cp16(bs + row * 128 + ((lc ^ (row & 7)) * 16),
                 B + (size_t)row * ldb + koff);
        }
        asm volatile("cp.async.commit_group;");
    };

    int nkb = K >> 6;
    issue_stage(0, 0);
    issue_stage(1, 1);
    if (nkb > 2) issue_stage(2, 2);
    else asm volatile("cp.async.commit_group;");

    int arow = wy * 32 + (lane & 15);
    int brow = wx * 32 + (lane & 15);
    int csel = lane >> 4;

    for (int kb = 0; kb < nkb; kb++) {
        asm volatile("cp.async.wait_group 2;");
        __syncthreads();
        int stage = kb % NSTAGE;
        if (kb + 3 < nkb) issue_stage(kb + 3, (kb + 3) % NSTAGE);
        else asm volatile("cp.async.commit_group;");

        uint32_t as = sb + stage * STAGE3;
        uint32_t bs = as + A3_BYTES;
        #pragma unroll
        for (int kk = 0; kk < 4; kk++) {
            int ch = kk * 2 + csel;
            uint32_t afr[2][4], breg[2][4];
            #pragma unroll
            for (int mi = 0; mi < 2; mi++) {
                int r = arow + mi * 16;
                ldsm_x4(afr[mi][0], afr[mi][1], afr[mi][2], afr[mi][3],
                        as + r * 128 + ((ch ^ (r & 7)) * 16));
            }
            #pragma unroll
            for (int p = 0; p < 2; p++) {
                int r = brow + p * 16;
                ldsm_x4(breg[p][0], breg[p][1], breg[p][2], breg[p][3],
                        bs + r * 128 + ((ch ^ (r & 7)) * 16));
            }
            #pragma unroll
            for (int mi = 0; mi < 2; mi++)
                #pragma unroll
                for (int ni = 0; ni < 4; ni++) {
                    uint32_t bfr[2] = { breg[ni >> 1][ni & 1], breg[ni >> 1][(ni & 1) + 2] };
                    mma_f16(acc[mi][ni], afr[mi], bfr);
                }
        }
    }

    #pragma unroll
    for (int mi = 0; mi < 2; mi++) {
        #pragma unroll
        for (int ni = 0; ni < 4; ni++) {
            int col = n0 + wx * 32 + ni * 8 + 2 * (lane & 3);
            #pragma unroll
            for (int half = 0; half < 2; half++) {
                int row = m0 + wy * 32 + mi * 16 + (lane >> 2) + half * 8;
                float c0 = acc[mi][ni][2 * half]     * scale;
                float c1 = acc[mi][ni][2 * half + 1] * scale;
                if (bias) { c0 += bias[col]; c1 += bias[col + 1]; }
                if (act == 1) { c0 = gelu_tanh(c0); c1 = gelu_tanh(c1); }
                if (res) {
                    float2 rv = *(const float2*)(res + (size_t)row * ldc + col);
                    c0 += rv.x; c1 += rv.y;
                }
                store2(C + (size_t)row * ldc + col, c0, c1);
            }
        }
    }
}

// -------- host launch: dual batch-half pipelines on TWO streams only ---------
extern "C" void kernel_launch(void* const* d_in, const int* in_sizes, int n_in,
                              void* d_out, int out_size) {
    const float* x     = (const float*)d_in[0];
    const float* zin   = (const float*)d_in[1];
    const float* g1    = (const float*)d_in[2];
    const float* b1    = (const float*)d_in[3];
    const float* w_qkv = (const float*)d_in[4];
    const float* b_qkv = (const float*)d_in[5];
    const float* w_o   = (const float*)d_in[6];
    const float* b_o   = (const float*)d_in[7];
    const float* w_kv  = (const float*)d_in[8];
    const float* b_kv  = (const float*)d_in[9];
    const float* g2    = (const float*)d_in[10];
    const float* b2    = (const float*)d_in[11];
    const float* w_m1  = (const float*)d_in[12];
    const float* b_m1  = (const float*)d_in[13];
    const float* w_m2  = (const float*)d_in[14];
    const float* b_m2  = (const float*)d_in[15];
    float* out = (float*)d_out;

    __half *ln, *qkv, *kv, *attn, *q, *mlp, *p, *z16;
    __half *wtqkv, *wto, *wtkv, *wtm1, *wtm2, *vts, *vtc;
    float *cross, *xs;
    cudaGetSymbolAddress((void**)&ln,     h_ln);
    cudaGetSymbolAddress((void**)&qkv,    h_qkv);
    cudaGetSymbolAddress((void**)&kv,     h_kv);
    cudaGetSymbolAddress((void**)&attn,   h_attn);
    cudaGetSymbolAddress((void**)&q,      h_q);
    cudaGetSymbolAddress((void**)&cross,  g_cross);
    cudaGetSymbolAddress((void**)&mlp,    h_mlp);
    cudaGetSymbolAddress((void**)&xs,     g_xs);
    cudaGetSymbolAddress((void**)&p,      h_p);
    cudaGetSymbolAddress((void**)&z16,    h_z);
    cudaGetSymbolAddress((void**)&wtqkv,  h_wt_qkv);
    cudaGetSymbolAddress((void**)&wto,    h_wt_o);
    cudaGetSymbolAddress((void**)&wtkv,   h_wt_kv);
    cudaGetSymbolAddress((void**)&wtm1,   h_wt_m1);
    cudaGetSymbolAddress((void**)&wtm2,   h_wt_m2);
    cudaGetSymbolAddress((void**)&vts,    h_vt_self);
    cudaGetSymbolAddress((void**)&vtc,    h_vt_cross);

    cudaFuncSetAttribute((const void*)mm2<__half, 256>, cudaFuncAttributeMaxDynamicSharedMemorySize, SMEM_T(256));
    cudaFuncSetAttribute((const void*)mm2<__half, 128>, cudaFuncAttributeMaxDynamicSharedMemorySize, SMEM_T(128));
    cudaFuncSetAttribute((const void*)mm3<__half>, cudaFuncAttributeMaxDynamicSharedMemorySize, SMEM3);
    cudaFuncSetAttribute((const void*)mm3<float>,  cudaFuncAttributeMaxDynamicSharedMemorySize, SMEM3);
    cudaFuncSetAttribute((const void*)flash_self,  cudaFuncAttributeMaxDynamicSharedMemorySize, FLASH_SMEM);

    // ONE extra stream (matches the zero-residual topology of R13-R15)
    cudaStream_t s2;
    cudaStreamCreateWithFlags(&s2, cudaStreamNonBlocking);
    cudaEvent_t evStart, evZA, evWQ, evWO, evKVA, evW, evEndB;
    cudaEventCreateWithFlags(&evStart, cudaEventDisableTiming);
    cudaEventCreateWithFlags(&evZA,  cudaEventDisableTiming);
    cudaEventCreateWithFlags(&evWQ,  cudaEventDisableTiming);
    cudaEventCreateWithFlags(&evWO,  cudaEventDisableTiming);
    cudaEventCreateWithFlags(&evKVA, cudaEventDisableTiming);
    cudaEventCreateWithFlags(&evW,   cudaEventDisableTiming);
    cudaEventCreateWithFlags(&evEndB,cudaEventDisableTiming);

    // per-half base offsets (half = 2 batches = 2048 rows)
    const size_t oD  = (size_t)HROWS * D_MODEL;
    const size_t o3D = (size_t)HROWS * 3 * D_MODEL;
    const size_t o2D = (size_t)HROWS * 2 * D_MODEL;
    const size_t oH  = (size_t)HROWS * HMLP;
    const size_t oS  = (size_t)2 * SEQ * SEQ;
    const size_t oVS = (size_t)2 * NHEADS * HDIM * SEQ;
    const size_t oVC = (size_t)2 * D_MODEL * SEQ;

    // ---- fork ----
    cudaEventRecord(evStart, 0);
    cudaStreamWaitEvent(s2, evStart, 0);

    // ---- main: ln1_A (also converts z half A) ----
    ln_kernel<<<HROWS, 256>>>(x, g1, b1, ln, zin, z16);
    cudaEventRecord(evZA, 0);

    // ================= s2: weights + kv_A release + full pipeline B ==========
    transpose64<float><<<dim3(48, 16, 1), 256, 0, s2>>>(w_qkv, wtqkv, 3 * D_MODEL, D_MODEL, 0, 0, 0, 0, 1);
    cudaEventRecord(evWQ, s2);
    transpose64<float><<<dim3(16, 16, 1), 256, 0, s2>>>(w_o, wto, D_MODEL, D_MODEL, 0, 0, 0, 0, 1);
    cudaEventRecord(evWO, s2);
    transpose64<float><<<dim3(32, 16, 1), 256, 0, s2>>>(w_kv, wtkv, 2 * D_MODEL, D_MODEL, 0, 0, 0, 0, 1);
    // ln1_B (+ z half B)
    ln_kernel<<<HROWS, 256, 0, s2>>>(x + oD, g1, b1, ln + oD, zin + oD, z16 + oD);
    // kv_A + vtc_A (released to pipeline A early)
    cudaStreamWaitEvent(s2, evZA, 0);
    mm2<__half, 256><<<dim3(8, 16, 1), 256, SMEM_T(256), s2>>>(
        z16, wtkv, b_kv, nullptr, kv, D_MODEL, D_MODEL, D_MODEL, 2 * D_MODEL,
        0, 0, 0, 1.0f, 0);
    transpose64<__half><<<dim3(16, 16, 2), 256, 0, s2>>>(
        kv + D_MODEL, vtc, 2 * D_MODEL, SEQ,
        (long)SEQ * 2 * D_MODEL, 0, (long)D_MODEL * SEQ, 0, 1);
    cudaEventRecord(evKVA, s2);
    // pipeline B (all deps stream-local from here)
    mm2<__half, 256><<<dim3(12, 16, 1), 256, SMEM_T(256), s2>>>(
        ln + oD, wtqkv, b_qkv, nullptr, qkv + o3D, D_MODEL, D_MODEL, D_MODEL, 3 * D_MODEL,
        0, 0, 0, 1.0f, 0);
    transpose64<__half><<<dim3(1, 16, 2 * NHEADS), 256, 0, s2>>>(
        qkv + o3D + 2 * D_MODEL, vts + oVS, 3 * D_MODEL, SEQ,
        (long)SEQ * 3 * D_MODEL, HDIM, (long)NHEADS * HDIM * SEQ, (long)HDIM * SEQ, NHEADS);
    flash_self<<<dim3(8, 2 * NHEADS), 256, FLASH_SMEM, s2>>>(qkv + o3D, vts + oVS, attn + oD);
    mm3<__half><<<dim3(16, 32, 1), 128, SMEM3, s2>>>(
        attn + oD, wto, b_o, x + oD, q + oD, D_MODEL, D_MODEL, D_MODEL, D_MODEL,
        0, 0, 0, 1.0f, 0);
    mm2<__half, 256><<<dim3(8, 16, 1), 256, SMEM_T(256), s2>>>(
        z16 + oD, wtkv, b_kv, nullptr, kv + o2D, D_MODEL, D_MODEL, D_MODEL, 2 * D_MODEL,
        0, 0, 0, 1.0f, 0);
    transpose64<__half><<<dim3(16, 16, 2), 256, 0, s2>>>(
        kv + o2D + D_MODEL, vtc + oVC, 2 * D_MODEL, SEQ,
        (long)SEQ * 2 * D_MODEL, 0, (long)D_MODEL * SEQ, 0, 1);
    mm3<float><<<dim3(16, 16, 2), 128, SMEM3, s2>>>(
        q + oD, kv + o2D, nullptr, nullptr, xs + oS, D_MODEL, D_MODEL, 2 * D_MODEL, SEQ,
        (long)SEQ * D_MODEL, (long)SEQ * 2 * D_MODEL, (long)SEQ * SEQ, 0.03125f, 0);
    softmax_f2h<<<2 * SEQ, 256, 0, s2>>>(xs + oS, p + oS);
    mm3<float><<<dim3(16, 16, 2), 128, SMEM3, s2>>>(
        p + oS, vtc + oVC, nullptr, nullptr, cross + oD, SEQ, SEQ, SEQ, D_MODEL,
        (long)SEQ * SEQ, (long)D_MODEL * SEQ, (long)SEQ * D_MODEL, 1.0f, 0);
    ln_kernel<<<HROWS, 256, 0, s2>>>(cross + oD, g2, b2, ln + oD, nullptr, nullptr);
    transpose64<float><<<dim3(64, 16, 1), 256, 0, s2>>>(w_m1, wtm1, HMLP, D_MODEL, 0, 0, 0, 0, 1);
    transpose64<float><<<dim3(16, 64, 1), 256, 0, s2>>>(w_m2, wtm2, D_MODEL, HMLP, 0, 0, 0, 0, 1);
    cudaEventRecord(evW, s2);
    mm2<__half, 128><<<dim3(32, 16, 1), 256, SMEM_T(128), s2>>>(
        ln + oD, wtm1, b_m1, nullptr, mlp + oH, D_MODEL, D_MODEL, D_MODEL, HMLP,
        0, 0, 0, 1.0f, 1);
    mm3<float><<<dim3(16, 32, 1), 128, SMEM3, s2>>>(
        mlp + oH, wtm2, b_m2, cross + oD, out + oD, HMLP, HMLP, HMLP, D_MODEL,
        0, 0, 0, 1.0f, 0);
    cudaEventRecord(evEndB, s2);

    // ================= main: pipeline A ==================
    cudaStreamWaitEvent(0, evWQ, 0);
    mm2<__half, 256><<<dim3(12, 16, 1), 256, SMEM_T(256)>>>(
        ln, wtqkv, b_qkv, nullptr, qkv, D_MODEL, D_MODEL, D_MODEL, 3 * D_MODEL,
        0, 0, 0, 1.0f, 0);
    transpose64<__half><<<dim3(1, 16, 2 * NHEADS), 256>>>(
        qkv + 2 * D_MODEL, vts, 3 * D_MODEL, SEQ,
        (long)SEQ * 3 * D_MODEL, HDIM, (long)NHEADS * HDIM * SEQ, (long)HDIM * SEQ, NHEADS);
    flash_self<<<dim3(8, 2 * NHEADS), 256, FLASH_SMEM>>>(qkv, vts, attn);
    cudaStreamWaitEvent(0, evWO, 0);
    mm3<__half><<<dim3(16, 32, 1), 128, SMEM3>>>(
        attn, wto, b_o, x, q, D_MODEL, D_MODEL, D_MODEL, D_MODEL,
        0, 0, 0, 1.0f, 0);
    cudaStreamWaitEvent(0, evKVA, 0);
    mm3<float><<<dim3(16, 16, 2), 128, SMEM3>>>(
        q, kv, nullptr, nullptr, xs, D_MODEL, D_MODEL, 2 * D_MODEL, SEQ,
        (long)SEQ * D_MODEL, (long)SEQ * 2 * D_MODEL, (long)SEQ * SEQ, 0.03125f, 0);
    softmax_f2h<<<2 * SEQ, 256>>>(xs, p);
    mm3<float><<<dim3(16, 16, 2), 128, SMEM3>>>(
        p, vtc, nullptr, nullptr, cross, SEQ, SEQ, SEQ, D_MODEL,
        (long)SEQ * SEQ, (long)D_MODEL * SEQ, (long)SEQ * D_MODEL, 1.0f, 0);
    ln_kernel<<<HROWS, 256>>>(cross, g2, b2, ln, nullptr, nullptr);
    cudaStreamWaitEvent(0, evW, 0);
    mm2<__half, 128><<<dim3(32, 16, 1), 256, SMEM_T(128)>>>(
        ln, wtm1, b_m1, nullptr, mlp, D_MODEL, D_MODEL, D_MODEL, HMLP,
        0, 0, 0, 1.0f, 1);
    mm3<float><<<dim3(16, 32, 1), 128, SMEM3>>>(
        mlp, wtm2, b_m2, cross, out, HMLP, HMLP, HMLP, D_MODEL,
        0, 0, 0, 1.0f, 0);

    // ---- join B back into origin before capture ends ----
    cudaStreamWaitEvent(0, evEndB, 0);
}